// round 5
// baseline (speedup 1.0000x reference)
#include <cuda_runtime.h>
#include <math.h>

// ---------------- problem constants ----------------
#define BATCH 2
#define IMH 128
#define IMW 160
#define HW (IMH*IMW)          // 20480
#define NT (BATCH*HW)         // 40960 tokens (one tensor)
#define NT2 (2*NT)            // 81920 tokens (ref+src concatenated, self layers)
#define DM 128
#define DFF 256
#define NHEADS 8
#define DH 16
#define NCHUNK 64
#define CHUNK (HW/NCHUNK)     // 320
#define SEGMAX 4              // max batch-segments (ref b0,b1, src b0,b1)

#define PE_SC (-0.14391156831212787f)   // -ln(10000)/64

typedef unsigned long long ull;

// packed f32x2 helpers (sm_103a FFMA2 path — ptxas never auto-fuses this)
__device__ __forceinline__ ull pack2(float lo, float hi) {
    ull r; asm("mov.b64 %0, {%1, %2};" : "=l"(r) : "f"(lo), "f"(hi)); return r;
}
__device__ __forceinline__ void unpack2(ull v, float& lo, float& hi) {
    asm("mov.b64 {%0, %1}, %2;" : "=f"(lo), "=f"(hi) : "l"(v));
}
#define FMA2(d, a, b) asm("fma.rn.f32x2 %0, %1, %2, %0;" : "+l"(d) : "l"(a), "l"(b))

// ---------------- scratch layout (floats) ----------------
#define BIGSZ  (NT*DM)                  // 5,242,880
#define S_GATE 0                        // 256
#define S_KV   256                      // SEGMAX*2048 = 8192
#define S_KSUM 8448                     // SEGMAX*128  = 512
#define S_KVP  8960                     // NCHUNK*SEGMAX*2048 = 524288
#define S_KSP  533248                   // NCHUNK*SEGMAX*128  = 32768
#define S_CTX  566016
#define S_CTX2 (S_CTX  + BIGSZ)
#define S_XREF (S_CTX2 + BIGSZ)
#define S_XSRC (S_XREF + BIGSZ)         // MUST stay contiguous after XREF
#define S_Q    (S_XSRC + BIGSZ)         // 2*BIGSZ each (sized for NT2)
#define S_K    (S_Q    + 2*BIGSZ)
#define S_V    (S_K    + 2*BIGSZ)
#define S_MSG  (S_V    + 2*BIGSZ)
#define S_X1   (S_MSG  + 2*BIGSZ)
#define S_FF   (S_X1   + 2*BIGSZ)       // NT2*DFF = 4*BIGSZ
#define S_TOTAL (S_FF + 4*BIGSZ)

__device__ float g_scratch[S_TOTAL];

// ---------------- camera-encoding gate (tiny MLP, per batch) ----------------
__global__ __launch_bounds__(128) void gate_kernel(
    const float* __restrict__ i2w, const float* __restrict__ bn1_g,
    const float* __restrict__ bn1_b,
    const float* __restrict__ fc1_w, const float* __restrict__ fc1_b,
    const float* __restrict__ fc2_w, const float* __restrict__ fc2_b,
    const float* __restrict__ ser_w, const float* __restrict__ ser_b,
    const float* __restrict__ see_w, const float* __restrict__ see_b,
    float* __restrict__ gate)
{
    int b = blockIdx.x;
    int o = threadIdx.x;
    __shared__ float m16[16];
    __shared__ float t[128];
    __shared__ float u[128];
    const float inv_std = rsqrtf(1.0f + 1e-5f);
    if (o < 16) m16[o] = i2w[b*16 + o] * inv_std * bn1_g[o] + bn1_b[o];
    __syncthreads();
    float a = fc1_b[o];
    #pragma unroll
    for (int j = 0; j < 16; j++) a += m16[j] * fc1_w[j*128 + o];
    t[o] = fmaxf(a, 0.0f);
    __syncthreads();
    a = fc2_b[o];
    for (int c = 0; c < 128; c++) a += t[c] * fc2_w[c*128 + o];
    u[o] = a;
    __syncthreads();
    a = ser_b[o];
    for (int c = 0; c < 128; c++) a += u[c] * ser_w[c*128 + o];
    __syncthreads();
    t[o] = fmaxf(a, 0.0f);
    __syncthreads();
    a = see_b[o];
    for (int c = 0; c < 128; c++) a += t[c] * see_w[c*128 + o];
    gate[b*128 + o] = 1.0f / (1.0f + expf(-a));
}

// ---------------- conv3x3(depth) -> BN/ReLU -> gate -> 1x1 conv -> ref_ctx (pixel-major) ----------------
__global__ __launch_bounds__(128) void ctx_kernel(
    const float* __restrict__ depth, const float* __restrict__ rc_w,
    const float* __restrict__ rc_b, const float* __restrict__ bn2_g,
    const float* __restrict__ bn2_b, const float* __restrict__ cc_w,
    const float* __restrict__ cc_b, const float* __restrict__ gate,
    float* __restrict__ ctx)
{
    int blk = blockIdx.x;                  // BATCH * HW/16 blocks
    int b = blk / (HW/16);
    int p0 = (blk % (HW/16)) * 16;         // 16 pixels, same row (16 | IMW)
    int y = p0 / IMW;
    int x0 = p0 % IMW;
    int c = threadIdx.x;
    __shared__ float h[16][128];

    float w9[9];
    #pragma unroll
    for (int i = 0; i < 9; i++) w9[i] = rc_w[c*9 + i];
    float rb = rc_b[c], g2 = bn2_g[c], b2 = bn2_b[c], gt = gate[b*128 + c];
    const float inv_std = rsqrtf(1.0f + 1e-5f);
    const float* dp = depth + (size_t)b * HW;

    for (int p = 0; p < 16; p++) {
        int x = x0 + p;
        float acc = rb;
        #pragma unroll
        for (int ky = 0; ky < 3; ky++) {
            int yy = y + ky - 1;
            if (yy < 0 || yy >= IMH) continue;
            #pragma unroll
            for (int kx = 0; kx < 3; kx++) {
                int xx = x + kx - 1;
                if (xx < 0 || xx >= IMW) continue;
                acc += dp[yy*IMW + xx] * w9[ky*3 + kx];
            }
        }
        h[p][c] = fmaxf(acc * inv_std * g2 + b2, 0.0f) * gt;
    }
    __syncthreads();

    int o = c;
    float acc[16];
    float cb = cc_b[o];
    #pragma unroll
    for (int p = 0; p < 16; p++) acc[p] = cb;
    for (int cc = 0; cc < 128; cc += 4) {
        float w0 = cc_w[(cc+0)*128 + o];
        float w1 = cc_w[(cc+1)*128 + o];
        float w2 = cc_w[(cc+2)*128 + o];
        float w3 = cc_w[(cc+3)*128 + o];
        #pragma unroll
        for (int p = 0; p < 16; p++) {
            float4 hv = *(const float4*)&h[p][cc];
            acc[p] += hv.x*w0 + hv.y*w1 + hv.z*w2 + hv.w*w3;
        }
    }
    #pragma unroll
    for (int p = 0; p < 16; p++)
        ctx[((size_t)b*HW + p0 + p)*DM + o] = acc[p];
}

// ---------------- homography warp: sample ref_ctx -> src_ctx (pixel-major) ----------------
__global__ __launch_bounds__(128) void warp_kernel(
    const float* __restrict__ ref_proj, const float* __restrict__ src_i2w,
    const float* __restrict__ depth, const float* __restrict__ ctx_in,
    float* __restrict__ ctx_out)
{
    int pix = blockIdx.x;        // NT blocks
    int b = pix / HW;
    int l = pix % HW;
    int y = l / IMW, x = l % IMW;
    __shared__ float P[12];
    int tid = threadIdx.x;
    if (tid < 12) {
        int i = tid / 4, j = tid % 4;
        float s = 0.0f;
        #pragma unroll
        for (int k = 0; k < 4; k++)
            s += ref_proj[b*16 + i*4 + k] * src_i2w[b*16 + k*4 + j];
        P[tid] = s;
    }
    __syncthreads();
    float d  = depth[(size_t)b*HW + l];
    float fx = (float)x, fy = (float)y;
    float px = (P[0]*fx + P[1]*fy + P[2])  * d + P[3];
    float py = (P[4]*fx + P[5]*fy + P[6])  * d + P[7];
    float pz = (P[8]*fx + P[9]*fy + P[10]) * d + P[11];
    if (pz == 0.0f) pz = 1e-9f;
    float xs = px / pz, ys = py / pz;
    float x0f = floorf(xs), y0f = floorf(ys);
    float wx = xs - x0f, wy = ys - y0f;

    int c = tid;
    float out = 0.0f;
    #pragma unroll
    for (int corner = 0; corner < 4; corner++) {
        int dx = corner & 1, dy = corner >> 1;
        float xa = x0f + (float)dx, ya = y0f + (float)dy;
        bool valid = (xa >= 0.0f) && (xa <= (float)(IMW-1)) &&
                     (ya >= 0.0f) && (ya <= (float)(IMH-1));
        float wgt = (dx ? wx : 1.0f - wx) * (dy ? wy : 1.0f - wy);
        if (valid) {
            int xi = (int)fminf(fmaxf(xa, 0.0f), (float)(IMW-1));
            int yi = (int)fminf(fmaxf(ya, 0.0f), (float)(IMH-1));
            out += wgt * ctx_in[((size_t)b*HW + yi*IMW + xi)*DM + c];
        }
    }
    ctx_out[((size_t)b*HW + l)*DM + c] = out;
}

// ---------------- token assembly: X = transpose(feature) + PE + ctx ----------------
__global__ __launch_bounds__(256) void assemble_kernel(
    const float* __restrict__ feat, const float* __restrict__ ctx,
    float* __restrict__ X)
{
    int blk = blockIdx.x;                   // BATCH * HW/32
    int b = blk / (HW/32);
    int p0 = (blk % (HW/32)) * 32;
    __shared__ float s[128][33];
    int tid = threadIdx.x;
    #pragma unroll
    for (int i = 0; i < 16; i++) {
        int e = tid + i*256;
        int cch = e >> 5;
        int p = e & 31;
        s[cch][p] = feat[((size_t)b*DM + cch)*HW + p0 + p];
    }
    __syncthreads();
    #pragma unroll
    for (int i = 0; i < 16; i++) {
        int e = tid + i*256;
        int p = e >> 7;
        int cch = e & 127;
        int l = p0 + p;
        int yy = l / IMW, xx = l % IMW;
        int ii = cch >> 2, r = cch & 3;
        float div = expf((float)(2*ii) * PE_SC);
        float arg = ((r < 2) ? (float)(xx + 1) : (float)(yy + 1)) * div;
        float pe = ((r & 1) == 0) ? sinf(arg) : cosf(arg);
        size_t idx = ((size_t)b*HW + l)*DM + cch;
        X[idx] = s[cch][p] + pe + ctx[idx];
    }
}

// ---------------- GEMM core: 64x128 tile, 256 threads, FFMA2 (f32x2) math ----------------
// Accumulators packed as row-pairs: acc2[rp][j] = (acc(row 2rp), acc(row 2rp+1)) for col j.
template<int K, int NW>
__device__ __forceinline__ void gemm_core(
    const float* __restrict__ A, const float* __restrict__ W,
    float (*As)[64], float (*Ws)[128],
    size_t m0, int n0, int tid, ull acc2[4][4])
{
    int tx = tid & 31, ty = tid >> 5;
    int arow = tid >> 2;
    int ak4  = (tid & 3) * 4;
    const float* Ap = A + (m0 + arow) * K + ak4;

    int kk1 = tid >> 5;            // 0..7
    int kk2 = kk1 + 8;             // 8..15
    int n4  = (tid & 31) * 4;
    const float* Wp1 = W + (size_t)kk1 * NW + n0 + n4;
    const float* Wp2 = W + (size_t)kk2 * NW + n0 + n4;

    float4 av = *(const float4*)Ap;
    float4 w1 = *(const float4*)Wp1;
    float4 w2 = *(const float4*)Wp2;

    constexpr int NC = K / 16;
    #pragma unroll
    for (int c = 0; c < NC; c++) {
        if (c) __syncthreads();
        As[ak4+0][arow] = av.x; As[ak4+1][arow] = av.y;
        As[ak4+2][arow] = av.z; As[ak4+3][arow] = av.w;
        *(float4*)&Ws[kk1][n4] = w1;
        *(float4*)&Ws[kk2][n4] = w2;
        __syncthreads();
        if (c + 1 < NC) {
            av = *(const float4*)(Ap + (c+1)*16);
            w1 = *(const float4*)(Wp1 + (size_t)(c+1)*16*NW);
            w2 = *(const float4*)(Wp2 + (size_t)(c+1)*16*NW);
        }
        #pragma unroll
        for (int kk = 0; kk < 16; kk++) {
            float4 wv = *(const float4*)&Ws[kk][tx*4];           // per-lane, conflict-free
            float4 a0 = *(const float4*)&As[kk][ty*8];           // warp-uniform broadcast
            float4 a1 = *(const float4*)&As[kk][ty*8+4];
            ull ap[4];                                           // row-pairs (aligned halves -> free)
            ap[0] = pack2(a0.x, a0.y); ap[1] = pack2(a0.z, a0.w);
            ap[2] = pack2(a1.x, a1.y); ap[3] = pack2(a1.z, a1.w);
            ull wd[4];                                           // duplicated W per column
            wd[0] = pack2(wv.x, wv.x); wd[1] = pack2(wv.y, wv.y);
            wd[2] = pack2(wv.z, wv.z); wd[3] = pack2(wv.w, wv.w);
            #pragma unroll
            for (int rp = 0; rp < 4; rp++) {
                FMA2(acc2[rp][0], ap[rp], wd[0]);
                FMA2(acc2[rp][1], ap[rp], wd[1]);
                FMA2(acc2[rp][2], ap[rp], wd[2]);
                FMA2(acc2[rp][3], ap[rp], wd[3]);
            }
        }
    }
}

// per-row epilogue: bias + optional residual + epi + optional LN + store
template<int NW, int EPI, bool RESID, bool LNORM>
__device__ __forceinline__ void epilogue_row(
    float z0, float z1, float z2, float z3,
    size_t m, int n, const float4& bv,
    const float* __restrict__ resid,
    const float4& gv, const float4& lv,
    float* __restrict__ C)
{
    z0 += bv.x; z1 += bv.y; z2 += bv.z; z3 += bv.w;
    if (RESID) {
        float4 rv = *(const float4*)(resid + m*NW + n);
        z0 += rv.x; z1 += rv.y; z2 += rv.z; z3 += rv.w;
    }
    if (EPI == 1) {
        z0 = (z0 > 0.0f) ? z0 + 1.0f : expf(z0);
        z1 = (z1 > 0.0f) ? z1 + 1.0f : expf(z1);
        z2 = (z2 > 0.0f) ? z2 + 1.0f : expf(z2);
        z3 = (z3 > 0.0f) ? z3 + 1.0f : expf(z3);
    } else if (EPI == 2) {
        z0 = fmaxf(z0, 0.0f); z1 = fmaxf(z1, 0.0f);
        z2 = fmaxf(z2, 0.0f); z3 = fmaxf(z3, 0.0f);
    }
    if (LNORM) {
        float s = z0 + z1 + z2 + z3;
        float q = z0*z0 + z1*z1 + z2*z2 + z3*z3;
        #pragma unroll
        for (int off = 16; off; off >>= 1) {
            s += __shfl_xor_sync(0xffffffffu, s, off);
            q += __shfl_xor_sync(0xffffffffu, q, off);
        }
        float mu  = s * (1.0f/128.0f);
        float var = q * (1.0f/128.0f) - mu*mu;
        float inv = rsqrtf(var + 1e-5f);
        z0 = (z0 - mu)*inv*gv.x + lv.x;
        z1 = (z1 - mu)*inv*gv.y + lv.y;
        z2 = (z2 - mu)*inv*gv.z + lv.z;
        z3 = (z3 - mu)*inv*gv.w + lv.w;
    }
    *(float4*)(C + m*NW + n) = make_float4(z0, z1, z2, z3);
}

// ---------------- generic fused GEMM (bias / elu+1 / relu / residual / LayerNorm) ----------------
template<int K, int NW, int EPI, bool RESID, bool LNORM>
__global__ __launch_bounds__(256) void gemm_kernel(
    const float* __restrict__ A, const float* __restrict__ W,
    const float* __restrict__ bias, const float* __restrict__ resid,
    float* __restrict__ C,
    const float* __restrict__ lng, const float* __restrict__ lnb)
{
    __shared__ float As[16][64];
    __shared__ float Ws[16][128];
    int tid = threadIdx.x;
    int tx = tid & 31, ty = tid >> 5;
    size_t m0 = (size_t)blockIdx.x * 64;
    int n0 = blockIdx.y * 128;

    ull acc2[4][4];
    ull z64 = pack2(0.0f, 0.0f);
    #pragma unroll
    for (int rp = 0; rp < 4; rp++)
        #pragma unroll
        for (int j = 0; j < 4; j++) acc2[rp][j] = z64;

    gemm_core<K, NW>(A, W, As, Ws, m0, n0, tid, acc2);

    int n = n0 + tx*4;
    float4 bv = *(const float4*)(bias + n);
    float4 gv = make_float4(0,0,0,0), lv = make_float4(0,0,0,0);
    if (LNORM) {
        gv = *(const float4*)(lng + n);
        lv = *(const float4*)(lnb + n);
    }
    #pragma unroll
    for (int rp = 0; rp < 4; rp++) {
        float zl[4], zh[4];
        #pragma unroll
        for (int j = 0; j < 4; j++) unpack2(acc2[rp][j], zl[j], zh[j]);
        size_t ml = m0 + ty*8 + rp*2;
        epilogue_row<NW,EPI,RESID,LNORM>(zl[0], zl[1], zl[2], zl[3], ml,   n, bv, resid, gv, lv, C);
        epilogue_row<NW,EPI,RESID,LNORM>(zh[0], zh[1], zh[2], zh[3], ml+1, n, bv, resid, gv, lv, C);
    }
}

// ---------------- batched Q/K/V projection (blockIdx.y = 0:Q 1:K 2:V) ----------------
__global__ __launch_bounds__(256) void qkv_kernel(
    const float* __restrict__ x, const float* __restrict__ s,
    const float* __restrict__ w, const float* __restrict__ bvec,
    float* __restrict__ q, float* __restrict__ k, float* __restrict__ v)
{
    __shared__ float As[16][64];
    __shared__ float Ws[16][128];
    int z = blockIdx.y;
    const float* A    = (z == 0) ? x : s;
    const float* W    = w + (size_t)z * 16384;
    const float* bias = bvec + z * 128;
    float* C          = (z == 0) ? q : (z == 1) ? k : v;

    int tid = threadIdx.x;
    int tx = tid & 31, ty = tid >> 5;
    size_t m0 = (size_t)blockIdx.x * 64;

    ull acc2[4][4];
    ull z64 = pack2(0.0f, 0.0f);
    #pragma unroll
    for (int rp = 0; rp < 4; rp++)
        #pragma unroll
        for (int j = 0; j < 4; j++) acc2[rp][j] = z64;

    gemm_core<128, 128>(A, W, As, Ws, m0, 0, tid, acc2);

    int n = tx*4;
    float4 bv = *(const float4*)(bias + n);
    float4 dummy = make_float4(0,0,0,0);
    bool elu = (z < 2);
    #pragma unroll
    for (int rp = 0; rp < 4; rp++) {
        float zl[4], zh[4];
        #pragma unroll
        for (int j = 0; j < 4; j++) unpack2(acc2[rp][j], zl[j], zh[j]);
        size_t ml = m0 + ty*8 + rp*2;
        if (elu) {
            epilogue_row<128,1,false,false>(zl[0], zl[1], zl[2], zl[3], ml,   n, bv, nullptr, dummy, dummy, C);
            epilogue_row<128,1,false,false>(zh[0], zh[1], zh[2], zh[3], ml+1, n, bv, nullptr, dummy, dummy, C);
        } else {
            epilogue_row<128,0,false,false>(zl[0], zl[1], zl[2], zl[3], ml,   n, bv, nullptr, dummy, dummy, C);
            epilogue_row<128,0,false,false>(zh[0], zh[1], zh[2], zh[3], ml+1, n, bv, nullptr, dummy, dummy, C);
        }
    }
}

// ---------------- linear-attention KV reduction (coalesced, deterministic 2-stage) ----------------
// grid = (NCHUNK, nseg); segment = one batch of one tensor (HW tokens), segments never mix.
__global__ __launch_bounds__(256) void kv_reduce(
    const float* __restrict__ Kb_, const float* __restrict__ Vb_,
    float* __restrict__ KVP, float* __restrict__ KSP)
{
    int ch = blockIdx.x, b = blockIdx.y;
    int nseg = gridDim.y;
    int tid = threadIdx.x;
    int d  = tid & 15;
    int m0 = ((tid >> 4) & 3) * 4;
    int h0 = (tid >> 6) * 2;
    __shared__ float sk[8][128];
    __shared__ float sv[8][128];
    float acc[2][4] = {};
    float ksum = 0.0f;
    const float* Kp = Kb_ + ((size_t)b * HW) * DM;
    const float* Vp = Vb_ + ((size_t)b * HW) * DM;
    int s0 = ch * CHUNK;
    for (int s = s0; s < s0 + CHUNK; s += 8) {
        #pragma unroll
        for (int r = 0; r < 8; r++) {
            if (tid < 128) {
                float vv = Kp[(size_t)(s + r) * DM + tid];
                sk[r][tid] = vv;
                ksum += vv;
            } else {
                sv[r][tid - 128] = Vp[(size_t)(s + r) * DM + tid - 128];
            }
        }
        __syncthreads();
        #pragma unroll
        for (int r = 0; r < 8; r++) {
            float k0 = sk[r][h0*16 + d];
            float k1 = sk[r][(h0+1)*16 + d];
            float4 v0 = *(const float4*)&sv[r][h0*16 + m0];
            float4 v1 = *(const float4*)&sv[r][(h0+1)*16 + m0];
            acc[0][0] += k0*v0.x; acc[0][1] += k0*v0.y;
            acc[0][2] += k0*v0.z; acc[0][3] += k0*v0.w;
            acc[1][0] += k1*v1.x; acc[1][1] += k1*v1.y;
            acc[1][2] += k1*v1.z; acc[1][3] += k1*v1.w;
        }
        __syncthreads();
    }
    size_t chb = (size_t)ch * nseg + b;
    #pragma unroll
    for (int hh = 0; hh < 2; hh++)
        #pragma unroll
        for (int j = 0; j < 4; j++)
            KVP[chb*2048 + (size_t)((h0+hh)*16 + m0 + j)*16 + d] = acc[hh][j];
    if (tid < 128)
        KSP[chb*128 + tid] = ksum;
}

__global__ void kv_final(const float* __restrict__ KVP, const float* __restrict__ KSP,
                         float* __restrict__ KVo, float* __restrict__ KSo, int nseg)
{
    int i = blockIdx.x * 256 + threadIdx.x;
    if (i < nseg*2048) {
        int b = i >> 11, r = i & 2047;
        float s = 0.0f;
        #pragma unroll
        for (int c = 0; c < NCHUNK; c++)
            s += KVP[((size_t)c*nseg + b)*2048 + r];
        KVo[i] = s;
    } else if (i < nseg*2048 + nseg*128) {
        int j = i - nseg*2048;
        int b = j >> 7, r = j & 127;
        float s = 0.0f;
        #pragma unroll
        for (int c = 0; c < NCHUNK; c++)
            s += KSP[((size_t)c*nseg + b)*128 + r];
        KSo[j] = s;
    }
}

// ---------------- attention message: msg = (Q . KV) / (Q . Ksum + eps) ----------------
// Warp per 16 tokens; segment b = tok/HW indexes KV/KS (works for any nseg).
__global__ __launch_bounds__(256) void msg_kernel(
    const float* __restrict__ Q, const float* __restrict__ KV,
    const float* __restrict__ KS, float* __restrict__ MSG)
{
    int tid = threadIdx.x;
    int warp = tid >> 5, lane = tid & 31;
    size_t tok0 = (size_t)blockIdx.x * 128 + warp * 16;   // 16 tokens per warp
    int b = (int)(tok0 / HW);                             // HW % 128 == 0, no straddle
    int h  = lane >> 2;                                   // head 0..7
    int m0 = (lane & 3) * 4;                              // 4 output channels in head

    float4 kv[4][4];
    #pragma unroll
    for (int j = 0; j < 4; j++)
        #pragma unroll
        for (int qq = 0; qq < 4; qq++)
            kv[j][qq] = *(const float4*)&KV[(size_t)b*2048 + (size_t)((h*16 + m0 + j)*16 + qq*4)];
    float4 ks[4];
    #pragma unroll
    for (int qq = 0; qq < 4; qq++)
        ks[qq] = *(const float4*)&KS[b*128 + h*16 + qq*4];

    for (int t = 0; t < 16; t++) {
        size_t row = (tok0 + t) * DM;
        float4 q[4];
        #pragma unroll
        for (int qq = 0; qq < 4; qq++)
            q[qq] = *(const float4*)&Q[row + h*16 + qq*4];
        float den = 1e-6f;
        #pragma unroll
        for (int qq = 0; qq < 4; qq++)
            den += q[qq].x*ks[qq].x + q[qq].y*ks[qq].y + q[qq].z*ks[qq].z + q[qq].w*ks[qq].w;
        float inv = 1.0f / den;
        float4 o;
        float* op = &o.x;
        #pragma unroll
        for (int j = 0; j < 4; j++) {
            float s = 0.0f;
            #pragma unroll
            for (int qq = 0; qq < 4; qq++)
                s += q[qq].x*kv[j][qq].x + q[qq].y*kv[j][qq].y +
                     q[qq].z*kv[j][qq].z + q[qq].w*kv[j][qq].w;
            op[j] = s * inv;
        }
        *(float4*)&MSG[row + h*16 + m0] = o;
    }
}

// ---------------- host-side driver (M tokens, M % 128 == 0, M/HW segments) ----------------
static void run_encoder(const float* x, const float* s, float* xout, int M,
                        const float* w, const float* bvec,
                        const float* fw1, const float* fb1,
                        const float* fw2, const float* fb2,
                        const float* lg, const float* lb,
                        float* base)
{
    float* q   = base + S_Q;
    float* k   = base + S_K;
    float* v   = base + S_V;
    float* msg = base + S_MSG;
    float* x1  = base + S_X1;
    float* ff  = base + S_FF;
    int nseg = M / HW;
    dim3 g1(M/64, 1), g2(M/64, 2), g3(M/64, 3);

    qkv_kernel<<<g3, 256>>>(x, s, w, bvec, q, k, v);
    kv_reduce<<<dim3(NCHUNK, nseg), 256>>>(k, v, base + S_KVP, base + S_KSP);
    kv_final<<<(nseg*2176 + 255)/256, 256>>>(base + S_KVP, base + S_KSP,
                                             base + S_KV, base + S_KSUM, nseg);
    msg_kernel<<<M/128, 256>>>(q, base + S_KV, base + S_KSUM, msg);
    // merge + residual(x) + LN1 -> x1
    gemm_kernel<128,128,0,true,true><<<g1,256>>>(msg, w + 3*16384, bvec + 384, x, x1, lg, lb);
    // FFN up + relu -> ff
    gemm_kernel<128,256,2,false,false><<<g2,256>>>(x1, fw1, fb1, nullptr, ff, nullptr, nullptr);
    // FFN down + residual(x1) + LN2 -> xout (new state)
    gemm_kernel<256,128,0,true,true><<<g1,256>>>(ff, fw2, fb2, x1, xout, lg + 128, lb + 128);
}

extern "C" void kernel_launch(void* const* d_in, const int* in_sizes, int n_in,
                              void* d_out, int out_size)
{
    (void)in_sizes; (void)n_in; (void)out_size;
    const float* ref_feature = (const float*)d_in[0];
    const float* src_feature = (const float*)d_in[1];
    const float* ref_proj    = (const float*)d_in[2];
    const float* ref_i2w     = (const float*)d_in[4];
    const float* src_i2w     = (const float*)d_in[5];
    const float* depth       = (const float*)d_in[6];
    const float* attn_w      = (const float*)d_in[7];
    const float* attn_b      = (const float*)d_in[8];
    const float* ffn_w1      = (const float*)d_in[9];
    const float* ffn_b1      = (const float*)d_in[10];
    const float* ffn_w2      = (const float*)d_in[11];
    const float* ffn_b2      = (const float*)d_in[12];
    const float* ln_g        = (const float*)d_in[13];
    const float* ln_b        = (const float*)d_in[14];
    const float* rc_w        = (const float*)d_in[15];
    const float* rc_b        = (const float*)d_in[16];
    const float* bn2_g       = (const float*)d_in[17];
    const float* bn2_b       = (const float*)d_in[18];
    const float* cc_w        = (const float*)d_in[19];
    const float* cc_b        = (const float*)d_in[20];
    const float* bn1_g       = (const float*)d_in[21];
    const float* bn1_b       = (const float*)d_in[22];
    const float* fc1_w       = (const float*)d_in[23];
    const float* fc1_b       = (const float*)d_in[24];
    const float* fc2_w       = (const float*)d_in[25];
    const float* fc2_b       = (const float*)d_in[26];
    const float* ser_w       = (const float*)d_in[27];
    const float* ser_b       = (const float*)d_in[28];
    const float* see_w       = (const float*)d_in[29];
    const float* see_b       = (const float*)d_in[30];

    float* base = nullptr;
    cudaGetSymbolAddress((void**)&base, g_scratch);
    float* out_ref = (float*)d_out;
    float* out_src = (float*)d_out + (size_t)NT*DM;

    // prelude: gate -> ref_ctx -> warp -> token assembly
    gate_kernel<<<BATCH, 128>>>(ref_i2w, bn1_g, bn1_b, fc1_w, fc1_b, fc2_w, fc2_b,
                                ser_w, ser_b, see_w, see_b, base + S_GATE);
    ctx_kernel<<<BATCH*(HW/16), 128>>>(depth, rc_w, rc_b, bn2_g, bn2_b, cc_w, cc_b,
                                       base + S_GATE, base + S_CTX);
    warp_kernel<<<NT, 128>>>(ref_proj, src_i2w, depth, base + S_CTX, base + S_CTX2);
    assemble_kernel<<<BATCH*(HW/32), 256>>>(ref_feature, base + S_CTX,  base + S_XREF);
    assemble_kernel<<<BATCH*(HW/32), 256>>>(src_feature, base + S_CTX2, base + S_XSRC);

    float* xr = base + S_XREF;
    float* xs = base + S_XSRC;     // contiguous after xr -> [xr; xs] is one NT2-token tensor
    for (int i = 0; i < 4; i++) {
        const float* w   = attn_w + (size_t)i*4*16384;
        const float* bb  = attn_b + (size_t)i*512;
        const float* fw1 = ffn_w1 + (size_t)i*128*256;
        const float* fb1 = ffn_b1 + (size_t)i*256;
        const float* fw2 = ffn_w2 + (size_t)i*256*128;
        const float* fb2 = ffn_b2 + (size_t)i*128;
        const float* lg  = ln_g   + (size_t)i*256;
        const float* lb  = ln_b   + (size_t)i*256;
        if (i == 0 || i == 2) {
            // self layers: ref and src are independent & share weights -> one batched pass
            run_encoder(xr, xr, xr, NT2, w, bb, fw1, fb1, fw2, fb2, lg, lb, base);
        } else if (i == 1) {               // cross: src uses UPDATED ref
            run_encoder(xr, xs, xr, NT, w, bb, fw1, fb1, fw2, fb2, lg, lb, base);
            run_encoder(xs, xr, xs, NT, w, bb, fw1, fb1, fw2, fb2, lg, lb, base);
        } else {                           // final cross layer: write straight to d_out
            run_encoder(xr, xs, out_ref, NT, w, bb, fw1, fb1, fw2, fb2, lg, lb, base);
            run_encoder(xs, out_ref, out_src, NT, w, bb, fw1, fb1, fw2, fb2, lg, lb, base);
        }
    }
}

// round 15
// speedup vs baseline: 1.2254x; 1.2254x over previous
#include <cuda_runtime.h>
#include <cuda_bf16.h>
#include <math.h>
#include <stdint.h>

// ---------------- problem constants ----------------
#define BATCH 2
#define IMH 128
#define IMW 160
#define HW (IMH*IMW)          // 20480
#define NT (BATCH*HW)         // 40960 tokens (one tensor)
#define NT2 (2*NT)            // 81920 tokens (ref+src concatenated, self layers)
#define DM 128
#define DFF 256
#define NHEADS 8
#define DH 16
#define NCHUNK 64
#define CHUNK (HW/NCHUNK)     // 320
#define SEGMAX 4

#define PE_SC (-0.14391156831212787f)   // -ln(10000)/64

// ---------------- scratch layout (floats) ----------------
#define BIGSZ  (NT*DM)                  // 5,242,880
#define S_GATE 0
#define S_KV   256                      // SEGMAX*2048
#define S_KSUM 8448                     // SEGMAX*128
#define S_KVP  8960                     // NCHUNK*SEGMAX*2048
#define S_KSP  533248                   // NCHUNK*SEGMAX*128
#define S_CTX  566016
#define S_CTX2 (S_CTX  + BIGSZ)
#define S_XREF (S_CTX2 + BIGSZ)
#define S_XSRC (S_XREF + BIGSZ)         // contiguous after XREF
#define S_Q    (S_XSRC + BIGSZ)
#define S_K    (S_Q    + 2*BIGSZ)
#define S_V    (S_K    + 2*BIGSZ)
#define S_MSG  (S_V    + 2*BIGSZ)
#define S_X1   (S_MSG  + 2*BIGSZ)
#define S_FF   (S_X1   + 2*BIGSZ)
#define S_TOTAL (S_FF + 4*BIGSZ)

__device__ float g_scratch[S_TOTAL];

// prepped weights: bf16 hi/lo, transposed to B[n][k] (n-major, k contiguous), plain layout
#define WP_ATTN 0
#define WP_F1   262144
#define WP_F2   393216
#define WP_TOTAL 524288
__device__ __align__(16) __nv_bfloat16 g_wh[WP_TOTAL];
__device__ __align__(16) __nv_bfloat16 g_wl[WP_TOTAL];

// ---------------- mma.sync GEMM smem layout (dynamic) ----------------
// bf16 tiles padded to 72 cols (stride 144B): bank = (4g+t) mod 32 -> conflict-free frags
#define SMB_AH 0
#define SMB_AL 9216      // 64*72*2
#define SMB_BH 18432
#define SMB_BL 36864
#define SMEM_MMA 55296   // also holds f32 out tile 64*132*4 = 33792 (reused after mainloop)

#define MMA_BF16(d, a0, a1, a2, a3, b0, b1) \
    asm volatile("mma.sync.aligned.m16n8k16.row.col.f32.bf16.bf16.f32 " \
        "{%0,%1,%2,%3}, {%4,%5,%6,%7}, {%8,%9}, {%0,%1,%2,%3};" \
        : "+f"((d)[0]), "+f"((d)[1]), "+f"((d)[2]), "+f"((d)[3]) \
        : "r"(a0), "r"(a1), "r"(a2), "r"(a3), "r"(b0), "r"(b1))

__device__ __forceinline__ void split2(float a, float b, uint32_t& h, uint32_t& l) {
    __nv_bfloat16 ha = __float2bfloat16(a), hb = __float2bfloat16(b);
    float ra = a - __bfloat162float(ha), rb = b - __bfloat162float(hb);
    __nv_bfloat16 la = __float2bfloat16(ra), lb = __float2bfloat16(rb);
    h = (uint32_t)__bfloat16_as_ushort(ha) | ((uint32_t)__bfloat16_as_ushort(hb) << 16);
    l = (uint32_t)__bfloat16_as_ushort(la) | ((uint32_t)__bfloat16_as_ushort(lb) << 16);
}

// ---------------- weight prep: fp32 W[K,N] -> bf16 hi/lo at [mat][n][k] ----------------
__global__ void wprep_kernel(const float* __restrict__ W,
                             __nv_bfloat16* __restrict__ dh, __nv_bfloat16* __restrict__ dl,
                             int K, int N, int total)
{
    int e = blockIdx.x * 256 + threadIdx.x;
    if (e >= total) return;
    int per = K * N;
    int mat = e / per, r = e % per;
    int k = r / N, n = r % N;
    float w = W[(size_t)mat * per + (size_t)k * N + n];
    __nv_bfloat16 h = __float2bfloat16(w);
    __nv_bfloat16 l = __float2bfloat16(w - __bfloat162float(h));
    size_t di = ((size_t)mat * N + n) * K + k;
    dh[di] = h;
    dl[di] = l;
}

// ---------------- mma.sync GEMM core: 64x128 tile, split-bf16 (3 terms), fused epilogue ----------------
// 8 warps: warp = m-strip (wid&3, 16 rows) x n-half (wid>>2, 64 cols). K staged in 64-chunks.
__device__ __forceinline__ void mma_core(
    const float* __restrict__ A,
    const __nv_bfloat16* __restrict__ Wh, const __nv_bfloat16* __restrict__ Wl, // [NW][KTOT]
    const float* __restrict__ bias, const float* __restrict__ resid,
    float* __restrict__ C, int NW,
    const float* __restrict__ lng, const float* __restrict__ lnb,
    int KTOT, int epi, size_t m0, int n0, char* sm)
{
    __nv_bfloat16* sAh = (__nv_bfloat16*)(sm + SMB_AH);
    __nv_bfloat16* sAl = (__nv_bfloat16*)(sm + SMB_AL);
    __nv_bfloat16* sBh = (__nv_bfloat16*)(sm + SMB_BH);
    __nv_bfloat16* sBl = (__nv_bfloat16*)(sm + SMB_BL);
    int tid = threadIdx.x, wid = tid >> 5, lane = tid & 31;
    int g = lane >> 2, t = lane & 3;
    int strip = wid & 3, nh = wid >> 2;

    float acc[8][4];
    #pragma unroll
    for (int j = 0; j < 8; j++)
        #pragma unroll
        for (int c = 0; c < 4; c++) acc[j][c] = 0.0f;

    int NC = KTOT >> 6;
    for (int kc = 0; kc < NC; kc++) {
        // stage A chunk [64 x 64] fp32 -> bf16 hi/lo
        const float* Ap = A + m0 * KTOT + kc * 64;
        #pragma unroll
        for (int i = 0; i < 4; i++) {
            int idx = tid + 256 * i;          // 1024 float4
            int row = idx >> 4, c4 = idx & 15;
            float4 v = *(const float4*)(Ap + (size_t)row * KTOT + c4 * 4);
            uint32_t h01, l01, h23, l23;
            split2(v.x, v.y, h01, l01);
            split2(v.z, v.w, h23, l23);
            *(uint2*)&sAh[row * 72 + c4 * 4] = make_uint2(h01, h23);
            *(uint2*)&sAl[row * 72 + c4 * 4] = make_uint2(l01, l23);
        }
        // stage B chunk [128 x 64] bf16 hi/lo (already [n][k] in global)
        const __nv_bfloat16* Bh = Wh + (size_t)n0 * KTOT + kc * 64;
        const __nv_bfloat16* Bl = Wl + (size_t)n0 * KTOT + kc * 64;
        #pragma unroll
        for (int i = 0; i < 4; i++) {
            int idx = tid + 256 * i;          // 1024 uint4
            int row = idx >> 3, c8 = idx & 7;
            *(uint4*)&sBh[row * 72 + c8 * 8] = *(const uint4*)(Bh + (size_t)row * KTOT + c8 * 8);
            *(uint4*)&sBl[row * 72 + c8 * 8] = *(const uint4*)(Bl + (size_t)row * KTOT + c8 * 8);
        }
        __syncthreads();

        #pragma unroll
        for (int ks = 0; ks < 4; ks++) {
            int kk = ks * 16 + 2 * t;
            int ra = (strip * 16 + g) * 72;
            int rb = (strip * 16 + g + 8) * 72;
            uint32_t ah0 = *(const uint32_t*)&sAh[ra + kk];
            uint32_t ah1 = *(const uint32_t*)&sAh[rb + kk];
            uint32_t ah2 = *(const uint32_t*)&sAh[ra + kk + 8];
            uint32_t ah3 = *(const uint32_t*)&sAh[rb + kk + 8];
            uint32_t al0 = *(const uint32_t*)&sAl[ra + kk];
            uint32_t al1 = *(const uint32_t*)&sAl[rb + kk];
            uint32_t al2 = *(const uint32_t*)&sAl[ra + kk + 8];
            uint32_t al3 = *(const uint32_t*)&sAl[rb + kk + 8];
            #pragma unroll
            for (int j = 0; j < 8; j++) {
                int n = (nh * 64 + j * 8 + g) * 72;
                uint32_t bh0 = *(const uint32_t*)&sBh[n + kk];
                uint32_t bh1 = *(const uint32_t*)&sBh[n + kk + 8];
                uint32_t bl0 = *(const uint32_t*)&sBl[n + kk];
                uint32_t bl1 = *(const uint32_t*)&sBl[n + kk + 8];
                MMA_BF16(acc[j], ah0, ah1, ah2, ah3, bh0, bh1);
                MMA_BF16(acc[j], al0, al1, al2, al3, bh0, bh1);
                MMA_BF16(acc[j], ah0, ah1, ah2, ah3, bl0, bl1);
            }
        }
        __syncthreads();
    }

    // spill accumulators to padded f32 smem tile [64][132] (reuses A/B region)
    float* sOut = (float*)sm;
    #pragma unroll
    for (int j = 0; j < 8; j++) {
        int col = nh * 64 + j * 8 + 2 * t;
        int r0 = strip * 16 + g, r1 = r0 + 8;
        sOut[r0 * 132 + col]     = acc[j][0];
        sOut[r0 * 132 + col + 1] = acc[j][1];
        sOut[r1 * 132 + col]     = acc[j][2];
        sOut[r1 * 132 + col + 1] = acc[j][3];
    }
    __syncthreads();

    // epilogue: 4 threads per row; thread q handles float4s at cols c*16 + q*4
    {
        int row = tid >> 2, q = tid & 3;
        float d[32];
        #pragma unroll
        for (int c = 0; c < 8; c++) {
            int col = c * 16 + q * 4;
            float4 v  = *(const float4*)&sOut[row * 132 + col];
            float4 bv = *(const float4*)(bias + n0 + col);
            d[4*c]   = v.x + bv.x; d[4*c+1] = v.y + bv.y;
            d[4*c+2] = v.z + bv.z; d[4*c+3] = v.w + bv.w;
        }
        size_t m = m0 + row;
        if (resid) {
            #pragma unroll
            for (int c = 0; c < 8; c++) {
                int col = c * 16 + q * 4;
                float4 rv = *(const float4*)(resid + m * NW + n0 + col);
                d[4*c]   += rv.x; d[4*c+1] += rv.y;
                d[4*c+2] += rv.z; d[4*c+3] += rv.w;
            }
        }
        if (epi == 1) {
            #pragma unroll
            for (int jj = 0; jj < 32; jj++)
                d[jj] = (d[jj] > 0.0f) ? d[jj] + 1.0f : expf(d[jj]);
        } else if (epi == 2) {
            #pragma unroll
            for (int jj = 0; jj < 32; jj++)
                d[jj] = fmaxf(d[jj], 0.0f);
        }
        if (lng) {   // full-row LN (NW==128, n0==0 for all LN uses)
            float s = 0.0f, qd = 0.0f;
            #pragma unroll
            for (int jj = 0; jj < 32; jj++) { s += d[jj]; qd += d[jj] * d[jj]; }
            s  += __shfl_xor_sync(0xffffffffu, s, 1);
            qd += __shfl_xor_sync(0xffffffffu, qd, 1);
            s  += __shfl_xor_sync(0xffffffffu, s, 2);
            qd += __shfl_xor_sync(0xffffffffu, qd, 2);
            float mu  = s * (1.0f / 128.0f);
            float var = qd * (1.0f / 128.0f) - mu * mu;
            float inv = rsqrtf(var + 1e-5f);
            #pragma unroll
            for (int c = 0; c < 8; c++) {
                int col = c * 16 + q * 4;
                float4 gv = *(const float4*)(lng + col);
                float4 bv = *(const float4*)(lnb + col);
                d[4*c]   = (d[4*c]   - mu) * inv * gv.x + bv.x;
                d[4*c+1] = (d[4*c+1] - mu) * inv * gv.y + bv.y;
                d[4*c+2] = (d[4*c+2] - mu) * inv * gv.z + bv.z;
                d[4*c+3] = (d[4*c+3] - mu) * inv * gv.w + bv.w;
            }
        }
        #pragma unroll
        for (int c = 0; c < 8; c++) {
            int col = c * 16 + q * 4;
            *(float4*)(C + m * NW + n0 + col) =
                make_float4(d[4*c], d[4*c+1], d[4*c+2], d[4*c+3]);
        }
    }
}

__global__ __launch_bounds__(256, 2)
void mma_gemm_kernel(const float* __restrict__ A,
                     const __nv_bfloat16* __restrict__ Wh, const __nv_bfloat16* __restrict__ Wl,
                     const float* __restrict__ bias, const float* __restrict__ resid,
                     float* __restrict__ C, int NW,
                     const float* __restrict__ lng, const float* __restrict__ lnb,
                     int KTOT, int epi)
{
    extern __shared__ char sm[];
    mma_core(A, Wh, Wl, bias, resid, C, NW, lng, lnb, KTOT, epi,
             (size_t)blockIdx.x * 64, blockIdx.y * 128, sm);
}

__global__ __launch_bounds__(256, 2)
void qkv_mma(const float* __restrict__ x, const float* __restrict__ s,
             const __nv_bfloat16* __restrict__ Wh, const __nv_bfloat16* __restrict__ Wl,
             const float* __restrict__ bvec,
             float* __restrict__ q, float* __restrict__ k, float* __restrict__ v)
{
    extern __shared__ char sm[];
    int z = blockIdx.y;
    const float* A = (z == 0) ? x : s;
    float* C = (z == 0) ? q : (z == 1) ? k : v;
    mma_core(A, Wh + (size_t)z * 16384, Wl + (size_t)z * 16384, bvec + z * 128, nullptr,
             C, 128, nullptr, nullptr, 128, (z < 2) ? 1 : 0,
             (size_t)blockIdx.x * 64, 0, sm);
}

// ---------------- prelude kernels (unchanged, verified on HW) ----------------
__global__ __launch_bounds__(128) void gate_kernel(
    const float* __restrict__ i2w, const float* __restrict__ bn1_g,
    const float* __restrict__ bn1_b,
    const float* __restrict__ fc1_w, const float* __restrict__ fc1_b,
    const float* __restrict__ fc2_w, const float* __restrict__ fc2_b,
    const float* __restrict__ ser_w, const float* __restrict__ ser_b,
    const float* __restrict__ see_w, const float* __restrict__ see_b,
    float* __restrict__ gate)
{
    int b = blockIdx.x;
    int o = threadIdx.x;
    __shared__ float m16[16];
    __shared__ float t[128];
    __shared__ float u[128];
    const float inv_std = rsqrtf(1.0f + 1e-5f);
    if (o < 16) m16[o] = i2w[b*16 + o] * inv_std * bn1_g[o] + bn1_b[o];
    __syncthreads();
    float a = fc1_b[o];
    #pragma unroll
    for (int j = 0; j < 16; j++) a += m16[j] * fc1_w[j*128 + o];
    t[o] = fmaxf(a, 0.0f);
    __syncthreads();
    a = fc2_b[o];
    for (int c = 0; c < 128; c++) a += t[c] * fc2_w[c*128 + o];
    u[o] = a;
    __syncthreads();
    a = ser_b[o];
    for (int c = 0; c < 128; c++) a += u[c] * ser_w[c*128 + o];
    __syncthreads();
    t[o] = fmaxf(a, 0.0f);
    __syncthreads();
    a = see_b[o];
    for (int c = 0; c < 128; c++) a += t[c] * see_w[c*128 + o];
    gate[b*128 + o] = 1.0f / (1.0f + expf(-a));
}

__global__ __launch_bounds__(128) void ctx_kernel(
    const float* __restrict__ depth, const float* __restrict__ rc_w,
    const float* __restrict__ rc_b, const float* __restrict__ bn2_g,
    const float* __restrict__ bn2_b, const float* __restrict__ cc_w,
    const float* __restrict__ cc_b, const float* __restrict__ gate,
    float* __restrict__ ctx)
{
    int blk = blockIdx.x;
    int b = blk / (HW/16);
    int p0 = (blk % (HW/16)) * 16;
    int y = p0 / IMW;
    int x0 = p0 % IMW;
    int c = threadIdx.x;
    __shared__ float h[16][128];

    float w9[9];
    #pragma unroll
    for (int i = 0; i < 9; i++) w9[i] = rc_w[c*9 + i];
    float rb = rc_b[c], g2 = bn2_g[c], b2 = bn2_b[c], gt = gate[b*128 + c];
    const float inv_std = rsqrtf(1.0f + 1e-5f);
    const float* dp = depth + (size_t)b * HW;

    for (int p = 0; p < 16; p++) {
        int x = x0 + p;
        float acc = rb;
        #pragma unroll
        for (int ky = 0; ky < 3; ky++) {
            int yy = y + ky - 1;
            if (yy < 0 || yy >= IMH) continue;
            #pragma unroll
            for (int kx = 0; kx < 3; kx++) {
                int xx = x + kx - 1;
                if (xx < 0 || xx >= IMW) continue;
                acc += dp[yy*IMW + xx] * w9[ky*3 + kx];
            }
        }
        h[p][c] = fmaxf(acc * inv_std * g2 + b2, 0.0f) * gt;
    }
    __syncthreads();

    int o = c;
    float acc[16];
    float cb = cc_b[o];
    #pragma unroll
    for (int p = 0; p < 16; p++) acc[p] = cb;
    for (int cc = 0; cc < 128; cc += 4) {
        float w0 = cc_w[(cc+0)*128 + o];
        float w1 = cc_w[(cc+1)*128 + o];
        float w2 = cc_w[(cc+2)*128 + o];
        float w3 = cc_w[(cc+3)*128 + o];
        #pragma unroll
        for (int p = 0; p < 16; p++) {
            float4 hv = *(const float4*)&h[p][cc];
            acc[p] += hv.x*w0 + hv.y*w1 + hv.z*w2 + hv.w*w3;
        }
    }
    #pragma unroll
    for (int p = 0; p < 16; p++)
        ctx[((size_t)b*HW + p0 + p)*DM + o] = acc[p];
}

__global__ __launch_bounds__(128) void warp_kernel(
    const float* __restrict__ ref_proj, const float* __restrict__ src_i2w,
    const float* __restrict__ depth, const float* __restrict__ ctx_in,
    float* __restrict__ ctx_out)
{
    int pix = blockIdx.x;
    int b = pix / HW;
    int l = pix % HW;
    int y = l / IMW, x = l % IMW;
    __shared__ float P[12];
    int tid = threadIdx.x;
    if (tid < 12) {
        int i = tid / 4, j = tid % 4;
        float s = 0.0f;
        #pragma unroll
        for (int k = 0; k < 4; k++)
            s += ref_proj[b*16 + i*4 + k] * src_i2w[b*16 + k*4 + j];
        P[tid] = s;
    }
    __syncthreads();
    float d  = depth[(size_t)b*HW + l];
    float fx = (float)x, fy = (float)y;
    float px = (P[0]*fx + P[1]*fy + P[2])  * d + P[3];
    float py = (P[4]*fx + P[5]*fy + P[6])  * d + P[7];
    float pz = (P[8]*fx + P[9]*fy + P[10]) * d + P[11];
    if (pz == 0.0f) pz = 1e-9f;
    float xs = px / pz, ys = py / pz;
    float x0f = floorf(xs), y0f = floorf(ys);
    float wx = xs - x0f, wy = ys - y0f;

    int c = tid;
    float out = 0.0f;
    #pragma unroll
    for (int corner = 0; corner < 4; corner++) {
        int dx = corner & 1, dy = corner >> 1;
        float xa = x0f + (float)dx, ya = y0f + (float)dy;
        bool valid = (xa >= 0.0f) && (xa <= (float)(IMW-1)) &&
                     (ya >= 0.0f) && (ya <= (float)(IMH-1));
        float wgt = (dx ? wx : 1.0f - wx) * (dy ? wy : 1.0f - wy);
        if (valid) {
            int xi = (int)fminf(fmaxf(xa, 0.0f), (float)(IMW-1));
            int yi = (int)fminf(fmaxf(ya, 0.0f), (float)(IMH-1));
            out += wgt * ctx_in[((size_t)b*HW + yi*IMW + xi)*DM + c];
        }
    }
    ctx_out[((size_t)b*HW + l)*DM + c] = out;
}

__global__ __launch_bounds__(256) void assemble_kernel(
    const float* __restrict__ feat, const float* __restrict__ ctx,
    float* __restrict__ X)
{
    int blk = blockIdx.x;
    int b = blk / (HW/32);
    int p0 = (blk % (HW/32)) * 32;
    __shared__ float s[128][33];
    int tid = threadIdx.x;
    #pragma unroll
    for (int i = 0; i < 16; i++) {
        int e = tid + i*256;
        int cch = e >> 5;
        int p = e & 31;
        s[cch][p] = feat[((size_t)b*DM + cch)*HW + p0 + p];
    }
    __syncthreads();
    #pragma unroll
    for (int i = 0; i < 16; i++) {
        int e = tid + i*256;
        int p = e >> 7;
        int cch = e & 127;
        int l = p0 + p;
        int yy = l / IMW, xx = l % IMW;
        int ii = cch >> 2, r = cch & 3;
        float div = expf((float)(2*ii) * PE_SC);
        float arg = ((r < 2) ? (float)(xx + 1) : (float)(yy + 1)) * div;
        float pe = ((r & 1) == 0) ? sinf(arg) : cosf(arg);
        size_t idx = ((size_t)b*HW + l)*DM + cch;
        X[idx] = s[cch][p] + pe + ctx[idx];
    }
}

// ---------------- linear-attention KV reduction + message (unchanged, verified on HW) ----------------
__global__ __launch_bounds__(256) void kv_reduce(
    const float* __restrict__ Kb_, const float* __restrict__ Vb_,
    float* __restrict__ KVP, float* __restrict__ KSP)
{
    int ch = blockIdx.x, b = blockIdx.y;
    int nseg = gridDim.y;
    int tid = threadIdx.x;
    int d  = tid & 15;
    int m0 = ((tid >> 4) & 3) * 4;
    int h0 = (tid >> 6) * 2;
    __shared__ float sk[8][128];
    __shared__ float sv[8][128];
    float acc[2][4] = {};
    float ksum = 0.0f;
    const float* Kp = Kb_ + ((size_t)b * HW) * DM;
    const float* Vp = Vb_ + ((size_t)b * HW) * DM;
    int s0 = ch * CHUNK;
    for (int s = s0; s < s0 + CHUNK; s += 8) {
        #pragma unroll
        for (int r = 0; r < 8; r++) {
            if (tid < 128) {
                float vv = Kp[(size_t)(s + r) * DM + tid];
                sk[r][tid] = vv;
                ksum += vv;
            } else {
                sv[r][tid - 128] = Vp[(size_t)(s + r) * DM + tid - 128];
            }
        }
        __syncthreads();
        #pragma unroll
        for (int r = 0; r < 8; r++) {
            float k0 = sk[r][h0*16 + d];
            float k1 = sk[r][(h0+1)*16 + d];
            float4 v0 = *(const float4*)&sv[r][h0*16 + m0];
            float4 v1 = *(const float4*)&sv[r][(h0+1)*16 + m0];
            acc[0][0] += k0*v0.x; acc[0][1] += k0*v0.y;
            acc[0][2] += k0*v0.z; acc[0][3] += k0*v0.w;
            acc[1][0] += k1*v1.x; acc[1][1] += k1*v1.y;
            acc[1][2] += k1*v1.z; acc[1][3] += k1*v1.w;
        }
        __syncthreads();
    }
    size_t chb = (size_t)ch * nseg + b;
    #pragma unroll
    for (int hh = 0; hh < 2; hh++)
        #pragma unroll
        for (int j = 0; j < 4; j++)
            KVP[chb*2048 + (size_t)((h0+hh)*16 + m0 + j)*16 + d] = acc[hh][j];
    if (tid < 128)
        KSP[chb*128 + tid] = ksum;
}

__global__ void kv_final(const float* __restrict__ KVP, const float* __restrict__ KSP,
                         float* __restrict__ KVo, float* __restrict__ KSo, int nseg)
{
    int i = blockIdx.x * 256 + threadIdx.x;
    if (i < nseg*2048) {
        int b = i >> 11, r = i & 2047;
        float s = 0.0f;
        #pragma unroll
        for (int c = 0; c < NCHUNK; c++)
            s += KVP[((size_t)c*nseg + b)*2048 + r];
        KVo[i] = s;
    } else if (i < nseg*2048 + nseg*128) {
        int j = i - nseg*2048;
        int b = j >> 7, r = j & 127;
        float s = 0.0f;
        #pragma unroll
        for (int c = 0; c < NCHUNK; c++)
            s += KSP[((size_t)c*nseg + b)*128 + r];
        KSo[j] = s;
    }
}

__global__ __launch_bounds__(256) void msg_kernel(
    const float* __restrict__ Q, const float* __restrict__ KV,
    const float* __restrict__ KS, float* __restrict__ MSG)
{
    int tid = threadIdx.x;
    int warp = tid >> 5, lane = tid & 31;
    size_t tok0 = (size_t)blockIdx.x * 128 + warp * 16;
    int b = (int)(tok0 / HW);
    int h  = lane >> 2;
    int m0 = (lane & 3) * 4;

    float4 kv[4][4];
    #pragma unroll
    for (int j = 0; j < 4; j++)
        #pragma unroll
        for (int qq = 0; qq < 4; qq++)
            kv[j][qq] = *(const float4*)&KV[(size_t)b*2048 + (size_t)((h*16 + m0 + j)*16 + qq*4)];
    float4 ks[4];
    #pragma unroll
    for (int qq = 0; qq < 4; qq++)
        ks[qq] = *(const float4*)&KS[b*128 + h*16 + qq*4];

    for (int t = 0; t < 16; t++) {
        size_t row = (tok0 + t) * DM;
        float4 q[4];
        #pragma unroll
        for (int qq = 0; qq < 4; qq++)
            q[qq] = *(const float4*)&Q[row + h*16 + qq*4];
        float den = 1e-6f;
        #pragma unroll
        for (int qq = 0; qq < 4; qq++)
            den += q[qq].x*ks[qq].x + q[qq].y*ks[qq].y + q[qq].z*ks[qq].z + q[qq].w*ks[qq].w;
        float inv = 1.0f / den;
        float4 o;
        float* op = &o.x;
        #pragma unroll
        for (int j = 0; j < 4; j++) {
            float s = 0.0f;
            #pragma unroll
            for (int qq = 0; qq < 4; qq++)
                s += q[qq].x*kv[j][qq].x + q[qq].y*kv[j][qq].y +
                     q[qq].z*kv[j][qq].z + q[qq].w*kv[j][qq].w;
            op[j] = s * inv;
        }
        *(float4*)&MSG[row + h*16 + m0] = o;
    }
}

// ---------------- host-side driver ----------------
static void run_encoder(const float* x, const float* s, float* xout, int M, int layer,
                        const float* bvec, const float* fb1, const float* fb2,
                        const float* lg, const float* lb,
                        float* base, __nv_bfloat16* wh, __nv_bfloat16* wl)
{
    float* q   = base + S_Q;
    float* k   = base + S_K;
    float* v   = base + S_V;
    float* msg = base + S_MSG;
    float* x1  = base + S_X1;
    float* ff  = base + S_FF;
    int nseg = M / HW;
    int GB = M / 64;

    __nv_bfloat16* whA = wh + WP_ATTN + (size_t)layer * 4 * 16384;
    __nv_bfloat16* wlA = wl + WP_ATTN + (size_t)layer * 4 * 16384;
    __nv_bfloat16* wh1 = wh + WP_F1 + (size_t)layer * 32768;
    __nv_bfloat16* wl1 = wl + WP_F1 + (size_t)layer * 32768;
    __nv_bfloat16* wh2 = wh + WP_F2 + (size_t)layer * 32768;
    __nv_bfloat16* wl2 = wl + WP_F2 + (size_t)layer * 32768;

    qkv_mma<<<dim3(GB, 3), 256, SMEM_MMA>>>(x, s, whA, wlA, bvec, q, k, v);
    kv_reduce<<<dim3(NCHUNK, nseg), 256>>>(k, v, base + S_KVP, base + S_KSP);
    kv_final<<<(nseg*2176 + 255)/256, 256>>>(base + S_KVP, base + S_KSP,
                                             base + S_KV, base + S_KSUM, nseg);
    msg_kernel<<<M/128, 256>>>(q, base + S_KV, base + S_KSUM, msg);
    // merge + residual(x) + LN1 -> x1
    mma_gemm_kernel<<<dim3(GB, 1), 256, SMEM_MMA>>>(msg, whA + 3*16384, wlA + 3*16384,
                                                    bvec + 384, x, x1, 128, lg, lb, 128, 0);
    // FFN up + relu -> ff (N=256: two n-tiles)
    mma_gemm_kernel<<<dim3(GB, 2), 256, SMEM_MMA>>>(x1, wh1, wl1, fb1, nullptr, ff, 256,
                                                    nullptr, nullptr, 128, 2);
    // FFN down + residual(x1) + LN2 -> xout (K=256)
    mma_gemm_kernel<<<dim3(GB, 1), 256, SMEM_MMA>>>(ff, wh2, wl2, fb2, x1, xout, 128,
                                                    lg + 128, lb + 128, 256, 0);
}

extern "C" void kernel_launch(void* const* d_in, const int* in_sizes, int n_in,
                              void* d_out, int out_size)
{
    (void)in_sizes; (void)n_in; (void)out_size;
    const float* ref_feature = (const float*)d_in[0];
    const float* src_feature = (const float*)d_in[1];
    const float* ref_proj    = (const float*)d_in[2];
    const float* ref_i2w     = (const float*)d_in[4];
    const float* src_i2w     = (const float*)d_in[5];
    const float* depth       = (const float*)d_in[6];
    const float* attn_w      = (const float*)d_in[7];
    const float* attn_b      = (const float*)d_in[8];
    const float* ffn_w1      = (const float*)d_in[9];
    const float* ffn_b1      = (const float*)d_in[10];
    const float* ffn_w2      = (const float*)d_in[11];
    const float* ffn_b2      = (const float*)d_in[12];
    const float* ln_g        = (const float*)d_in[13];
    const float* ln_b        = (const float*)d_in[14];
    const float* rc_w        = (const float*)d_in[15];
    const float* rc_b        = (const float*)d_in[16];
    const float* bn2_g       = (const float*)d_in[17];
    const float* bn2_b       = (const float*)d_in[18];
    const float* cc_w        = (const float*)d_in[19];
    const float* cc_b        = (const float*)d_in[20];
    const float* bn1_g       = (const float*)d_in[21];
    const float* bn1_b       = (const float*)d_in[22];
    const float* fc1_w       = (const float*)d_in[23];
    const float* fc1_b       = (const float*)d_in[24];
    const float* fc2_w       = (const float*)d_in[25];
    const float* fc2_b       = (const float*)d_in[26];
    const float* ser_w       = (const float*)d_in[27];
    const float* ser_b       = (const float*)d_in[28];
    const float* see_w       = (const float*)d_in[29];
    const float* see_b       = (const float*)d_in[30];

    cudaFuncSetAttribute(mma_gemm_kernel, cudaFuncAttributeMaxDynamicSharedMemorySize, SMEM_MMA);
    cudaFuncSetAttribute(qkv_mma, cudaFuncAttributeMaxDynamicSharedMemorySize, SMEM_MMA);

    float* base = nullptr;
    cudaGetSymbolAddress((void**)&base, g_scratch);
    __nv_bfloat16* wh = nullptr;
    __nv_bfloat16* wl = nullptr;
    cudaGetSymbolAddress((void**)&wh, g_wh);
    cudaGetSymbolAddress((void**)&wl, g_wl);
    float* out_ref = (float*)d_out;
    float* out_src = (float*)d_out + (size_t)NT*DM;

    // weight prep: fp32 -> split-bf16, transposed to [n][k]
    wprep_kernel<<<1024, 256>>>(attn_w, wh + WP_ATTN, wl + WP_ATTN, 128, 128, 262144);
    wprep_kernel<<<512, 256>>>(ffn_w1, wh + WP_F1, wl + WP_F1, 128, 256, 131072);
    wprep_kernel<<<512, 256>>>(ffn_w2, wh + WP_F2, wl + WP_F2, 256, 128, 131072);

    // prelude: gate -> ref_ctx -> warp -> token assembly
    gate_kernel<<<BATCH, 128>>>(ref_i2w, bn1_g, bn1_b, fc1_w, fc1_b, fc2_w, fc2_b,
                                ser_w, ser_b, see_w, see_b, base + S_GATE);
    ctx_kernel<<<BATCH*(HW/16), 128>>>(depth, rc_w, rc_b, bn2_g, bn2_b, cc_w, cc_b,
                                       base + S_GATE, base + S_CTX);
    warp_kernel<<<NT, 128>>>(ref_proj, src_i2w, depth, base + S_CTX, base + S_CTX2);
    assemble_kernel<<<BATCH*(HW/32), 256>>>(ref_feature, base + S_CTX,  base + S_XREF);
    assemble_kernel<<<BATCH*(HW/32), 256>>>(src_feature, base + S_CTX2, base + S_XSRC);

    float* xr = base + S_XREF;
    float* xs = base + S_XSRC;
    for (int i = 0; i < 4; i++) {
        const float* bb  = attn_b + (size_t)i*512;
        const float* fb1 = ffn_b1 + (size_t)i*256;
        const float* fb2 = ffn_b2 + (size_t)i*128;
        const float* lg  = ln_g   + (size_t)i*256;
        const float* lb  = ln_b   + (size_t)i*256;
        if (i == 0 || i == 2) {
            // self layers: ref+src batched as one NT2-token tensor
            run_encoder(xr, xr, xr, NT2, i, bb, fb1, fb2, lg, lb, base, wh, wl);
        } else if (i == 1) {
            run_encoder(xr, xs, xr, NT, i, bb, fb1, fb2, lg, lb, base, wh, wl);
            run_encoder(xs, xr, xs, NT, i, bb, fb1, fb2, lg, lb, base, wh, wl);
        } else {
            run_encoder(xr, xs, out_ref, NT, i, bb, fb1, fb2, lg, lb, base, wh, wl);
            run_encoder(xs, out_ref, out_src, NT, i, bb, fb1, fb2, lg, lb, base, wh, wl);
        }
    }
}